// round 6
// baseline (speedup 1.0000x reference)
#include <cuda_runtime.h>
#include <cstdint>
#include <cstddef>

// ---------------------------------------------------------------------------
// metaLinear: y[t,o] = sum_j x2[t,j] * ( sum_i x1[t,i]*W[j*64+o,i] + bvec[j*64+o] )
// tokens = 16384, IN1=256, IN2=64, OUT=64.
//
// mma.sync m16n8k8 tf32 (virtual arch compute_103; tcgen05 unavailable).
// Per-CTA 128-token tile, 64 j-chunks of N=64, K=256. W prepacked fragment-
// major, streamed via cp.async.bulk + 6-stage mbarrier ring.
// 8 compute warps = 4 token-groups x 2 K-HALVES; every warp consumes every
// stage in the same global order (uniform protocol, empty count=8).
// k-half partial folds with x2 independently; acc summed once at the end.
// ---------------------------------------------------------------------------

#define TOK_TILE 128
#define NCHUNK   64
#define NST      6

#define OFF_MBAR 16
#define OFF_A    1024                       // 128 KB x1 fragments (4 groups)
#define OFF_B    (OFF_A + 131072)           // 48 KB: NST x 8192 B ring
#define OFF_X2   (OFF_B + NST * 8192)       // 32 KB: x2 [chunk][token]
#define OFF_BV   (OFF_X2 + 33280)           // 16 KB: bias
#define SMEM_TOTAL (OFF_BV + 16384)         // 230912 bytes

__device__ __align__(1024) static float g_Wpk[4096 * 256];   // prepacked W (4 MB)

// ---------------------------- helpers --------------------------------------

static __device__ __forceinline__ uint32_t smem_u32(const void* p) {
    uint32_t a;
    asm("{ .reg .u64 t; cvta.to.shared.u64 t, %1; cvt.u32.u64 %0, t; }"
        : "=r"(a) : "l"(p));
    return a;
}
static __device__ __forceinline__ void mbar_init(uint32_t m, uint32_t cnt) {
    asm volatile("mbarrier.init.shared.b64 [%0], %1;" :: "r"(m), "r"(cnt) : "memory");
}
static __device__ __forceinline__ void mbar_arrive(uint32_t m) {
    asm volatile("mbarrier.arrive.shared.b64 _, [%0];" :: "r"(m) : "memory");
}
static __device__ __forceinline__ void mbar_expect_tx(uint32_t m, uint32_t bytes) {
    asm volatile("mbarrier.arrive.expect_tx.shared.b64 _, [%0], %1;"
                 :: "r"(m), "r"(bytes) : "memory");
}
static __device__ __forceinline__ void mbar_wait(uint32_t m, uint32_t parity) {
    asm volatile(
        "{\n\t"
        ".reg .pred P;\n\t"
        "LAB_%=:\n\t"
        "mbarrier.try_wait.parity.acquire.cta.shared::cta.b64 P, [%0], %1, 0x989680;\n\t"
        "@P bra DONE_%=;\n\t"
        "bra LAB_%=;\n\t"
        "DONE_%=:\n\t"
        "}"
        :: "r"(m), "r"(parity) : "memory");
}
static __device__ __forceinline__ void bulk_g2s(uint32_t dst, const void* src,
                                                uint32_t bytes, uint32_t mbar) {
    asm volatile(
        "cp.async.bulk.shared::cluster.global.mbarrier::complete_tx::bytes "
        "[%0], [%1], %2, [%3];"
        :: "r"(dst), "l"(src), "r"(bytes), "r"(mbar) : "memory");
}
static __device__ __forceinline__ uint32_t f2tf32(float v) {
    uint32_t u;
    asm("cvt.rna.tf32.f32 %0, %1;" : "=r"(u) : "f"(v));
    return u;
}
static __device__ __forceinline__ void mma_frag_tf32(float* d, const uint32_t* a,
                                                     uint32_t b0, uint32_t b1) {
    asm volatile(
        "mma.sync.aligned.m16n8k8.row.col.f32.tf32.tf32.f32 "
        "{%0,%1,%2,%3}, {%4,%5,%6,%7}, {%8,%9}, {%0,%1,%2,%3};"
        : "+f"(d[0]), "+f"(d[1]), "+f"(d[2]), "+f"(d[3])
        : "r"(a[0]), "r"(a[1]), "r"(a[2]), "r"(a[3]), "r"(b0), "r"(b1));
}

// ------------------------ kernel 1: prepack W ------------------------------
// fragment-major for mma.sync m16n8k8 B operand (col-major k8 x n8):
// [chunk(64)][stage(8)][kstep(4)][ntile_pair(4)][lane(32)][4 words]

__global__ void prepack_w_kernel(const float* __restrict__ W) {
    int idx = blockIdx.x * 256 + threadIdx.x;   // 0 .. 1048575
    uint32_t u = f2tf32(W[idx]);
    int r  = idx >> 8;
    int cc = idx & 255;
    int chunk = r >> 6, o = r & 63;
    int ntile = o >> 3, c8o = o & 7;
    int kg = cc >> 3, stage = kg >> 2, kst = kg & 3, r8 = cc & 7;
    int lane = c8o * 4 + (r8 & 3);
    int reg  = r8 >> 2;
    int np   = ntile >> 1;
    int val  = ((ntile & 1) << 1) | reg;
    size_t off = ((((size_t)(chunk * 8 + stage) * 4 + kst) * 4 + np) * 32 + lane) * 16
                 + (size_t)val * 4;
    *reinterpret_cast<uint32_t*>(reinterpret_cast<char*>(g_Wpk) + off) = u;
}

// --------------------------- main kernel -----------------------------------
// 128 CTAs x 288 threads.
//   warps 0-7 : compute. g = wid&3 (32-token group), kh = wid>>2 (k-half).
//               Every warp consumes every stage; warp does ksteps {2kh,2kh+1}.
//   warp 8    : producer (cp.async.bulk), lane 0.

__global__ void __launch_bounds__(288, 1)
meta_main_kernel(const float* __restrict__ x1, const float* __restrict__ x2,
                 const float* __restrict__ bvec, float* __restrict__ out) {
    extern __shared__ __align__(1024) char smem[];
    const uint32_t sb = smem_u32(smem);
    const int tid  = threadIdx.x;
    const int wid  = tid >> 5;
    const int lane = tid & 31;
    const int cta  = blockIdx.x;
    const uint32_t MB = sb + OFF_MBAR;
    // full[s] = MB + 8s ; empty[s] = MB + 64 + 8s (count = 8 compute warps)

    if (tid == 0) {
        for (int s = 0; s < NST; s++) { mbar_init(MB + s * 8, 1); mbar_init(MB + 64 + s * 8, 8); }
    }

    // ---- prologue: pack x1 fragment-major (A operand m16n8k8 row-major) ----
    // layout: [group(4)][kstep(32)][mtile(2)][lane(32)][4 words] = 128 KB
    const float* x1p = x1 + (size_t)cta * (TOK_TILE * 256);
    for (int i = tid; i < TOK_TILE * 256; i += 288) {
        int t = i >> 8, c = i & 255;
        int g = t >> 5, mt = (t >> 4) & 1, r16 = t & 15;
        int kg = c >> 3, c8 = c & 7;
        int ln  = (r16 & 7) * 4 + (c8 & 3);
        int reg = ((r16 >> 3) & 1) | (((c8 >> 2) & 1) << 1);
        uint32_t off = (uint32_t)(((((g * 32 + kg) * 2 + mt) * 32 + ln) << 4) + (reg << 2));
        *reinterpret_cast<uint32_t*>(smem + OFF_A + off) = f2tf32(x1p[i]);
    }
    // x2 transposed: [chunk(64)][token(128)]
    const float* x2p = x2 + (size_t)cta * (TOK_TILE * 64);
    float* sx2 = reinterpret_cast<float*>(smem + OFF_X2);
    for (int i = tid; i < TOK_TILE * 64; i += 288) {
        int t = i >> 6, j = i & 63;
        sx2[j * 128 + t] = x2p[i];
    }
    float* sbv = reinterpret_cast<float*>(smem + OFF_BV);
    for (int i = tid; i < 4096; i += 288) sbv[i] = bvec[i];

    asm volatile("fence.proxy.async.shared::cta;" ::: "memory");
    __syncthreads();

    float acc[64];

    if (wid == 8) {
        // -------- producer: stream prepacked W, 8 KB stages, global order ----
        if (lane == 0) {
            const char* src = reinterpret_cast<const char*>(g_Wpk);
            for (int t = 0; t < NCHUNK * 8; t++) {
                int s = t % NST, u = t / NST;
                if (u > 0) mbar_wait(MB + 64 + s * 8, (u + 1) & 1);
                mbar_expect_tx(MB + s * 8, 8192);
                bulk_g2s(sb + OFF_B + s * 8192, src + (size_t)t * 8192, 8192, MB + s * 8);
            }
        }
    } else {
        const int g  = wid & 3;       // token group (32 tokens)
        const int kh = wid >> 2;      // k-half: ksteps {2kh, 2kh+1} per stage
#pragma unroll
        for (int v = 0; v < 64; v++) acc[v] = 0.0f;

        const char* aW = smem + OFF_A + g * 32768 + lane * 16;
        const int r = lane >> 2, q = lane & 3;

        for (int c = 0; c < NCHUNK; c++) {
            // chunk accumulator: k-half 0 carries the bias, half 1 starts at 0
            float C[64];
            if (kh == 0) {
                const float* bvc = sbv + c * 64;
#pragma unroll
                for (int n = 0; n < 8; n++) {
                    float bb0 = bvc[n * 8 + q * 2];
                    float bb1 = bvc[n * 8 + q * 2 + 1];
                    C[n * 4 + 0] = bb0; C[n * 4 + 1] = bb1;
                    C[n * 4 + 2] = bb0; C[n * 4 + 3] = bb1;
                    C[32 + n * 4 + 0] = bb0; C[32 + n * 4 + 1] = bb1;
                    C[32 + n * 4 + 2] = bb0; C[32 + n * 4 + 3] = bb1;
                }
            } else {
#pragma unroll
                for (int v = 0; v < 64; v++) C[v] = 0.0f;
            }

            for (int st = 0; st < 8; st++) {
                int t = c * 8 + st;
                int s = t % NST;
                mbar_wait(MB + s * 8, (t / NST) & 1);
                const char* bS = smem + OFF_B + s * 8192 + lane * 16;
#pragma unroll
                for (int kk = 0; kk < 2; kk++) {
                    int k  = kh * 2 + kk;
                    int kg = st * 4 + k;
                    uint4 a0 = *reinterpret_cast<const uint4*>(aW + kg * 1024);
                    uint4 a1 = *reinterpret_cast<const uint4*>(aW + kg * 1024 + 512);
                    uint4 bq0 = *reinterpret_cast<const uint4*>(bS + k * 2048);
                    uint4 bq1 = *reinterpret_cast<const uint4*>(bS + k * 2048 + 512);
                    uint4 bq2 = *reinterpret_cast<const uint4*>(bS + k * 2048 + 1024);
                    uint4 bq3 = *reinterpret_cast<const uint4*>(bS + k * 2048 + 1536);
                    const uint32_t* A0 = reinterpret_cast<const uint32_t*>(&a0);
                    const uint32_t* A1 = reinterpret_cast<const uint32_t*>(&a1);
                    mma_frag_tf32(C +  0, A0, bq0.x, bq0.y);
                    mma_frag_tf32(C +  4, A0, bq0.z, bq0.w);
                    mma_frag_tf32(C +  8, A0, bq1.x, bq1.y);
                    mma_frag_tf32(C + 12, A0, bq1.z, bq1.w);
                    mma_frag_tf32(C + 16, A0, bq2.x, bq2.y);
                    mma_frag_tf32(C + 20, A0, bq2.z, bq2.w);
                    mma_frag_tf32(C + 24, A0, bq3.x, bq3.y);
                    mma_frag_tf32(C + 28, A0, bq3.z, bq3.w);
                    mma_frag_tf32(C + 32, A1, bq0.x, bq0.y);
                    mma_frag_tf32(C + 36, A1, bq0.z, bq0.w);
                    mma_frag_tf32(C + 40, A1, bq1.x, bq1.y);
                    mma_frag_tf32(C + 44, A1, bq1.z, bq1.w);
                    mma_frag_tf32(C + 48, A1, bq2.x, bq2.y);
                    mma_frag_tf32(C + 52, A1, bq2.z, bq2.w);
                    mma_frag_tf32(C + 56, A1, bq3.x, bq3.y);
                    mma_frag_tf32(C + 60, A1, bq3.z, bq3.w);
                }
                __syncwarp();
                if (lane == 0) mbar_arrive(MB + 64 + s * 8);
            }

            // fold this k-half's chunk partial into acc: acc += x2[t,c] * C
            const float* xrow = sx2 + c * 128 + g * 32;
            float xv00 = xrow[r];
            float xv01 = xrow[r + 8];
            float xv10 = xrow[r + 16];
            float xv11 = xrow[r + 24];
#pragma unroll
            for (int n = 0; n < 8; n++) {
                acc[n * 4 + 0] = fmaf(xv00, C[n * 4 + 0], acc[n * 4 + 0]);
                acc[n * 4 + 1] = fmaf(xv00, C[n * 4 + 1], acc[n * 4 + 1]);
                acc[n * 4 + 2] = fmaf(xv01, C[n * 4 + 2], acc[n * 4 + 2]);
                acc[n * 4 + 3] = fmaf(xv01, C[n * 4 + 3], acc[n * 4 + 3]);
                acc[32 + n * 4 + 0] = fmaf(xv10, C[32 + n * 4 + 0], acc[32 + n * 4 + 0]);
                acc[32 + n * 4 + 1] = fmaf(xv10, C[32 + n * 4 + 1], acc[32 + n * 4 + 1]);
                acc[32 + n * 4 + 2] = fmaf(xv11, C[32 + n * 4 + 2], acc[32 + n * 4 + 2]);
                acc[32 + n * 4 + 3] = fmaf(xv11, C[32 + n * 4 + 3], acc[32 + n * 4 + 3]);
            }
        }
    }

    // ---- combine k-half partials (reuse dead A region, transposed) ----
    __syncthreads();
    float* xch = reinterpret_cast<float*>(smem + OFF_A);
    if (wid >= 4 && wid < 8) {
        int tb = (wid & 3) * 32 + lane;
#pragma unroll
        for (int v = 0; v < 64; v++) xch[v * 128 + tb] = acc[v];
    }
    __syncthreads();
    if (wid < 4) {
        int tb = wid * 32 + lane;
#pragma unroll
        for (int v = 0; v < 64; v++) acc[v] += xch[v * 128 + tb];

        const int r = lane >> 2, q = lane & 3;
        int trow = cta * TOK_TILE + wid * 32 + r;
#pragma unroll
        for (int m = 0; m < 2; m++) {
#pragma unroll
            for (int n = 0; n < 8; n++) {
                float2 v0 = make_float2(acc[m * 32 + n * 4 + 0], acc[m * 32 + n * 4 + 1]);
                float2 v1 = make_float2(acc[m * 32 + n * 4 + 2], acc[m * 32 + n * 4 + 3]);
                *reinterpret_cast<float2*>(out + (size_t)(trow + m * 16) * 64 + n * 8 + q * 2) = v0;
                *reinterpret_cast<float2*>(out + (size_t)(trow + m * 16 + 8) * 64 + n * 8 + q * 2) = v1;
            }
        }
    }
}

// ------------------------------ launcher -----------------------------------

extern "C" void kernel_launch(void* const* d_in, const int* in_sizes, int n_in,
                              void* d_out, int out_size) {
    const float* x1 = (const float*)d_in[0];   // (4,4096,256)
    const float* x2 = (const float*)d_in[1];   // (4,4096,64)
    const float* W  = (const float*)d_in[2];   // (4096,256)
    const float* bv = (const float*)d_in[3];   // (4096,)
    float* out = (float*)d_out;                // (4,4096,64)

    cudaFuncSetAttribute(meta_main_kernel,
                         cudaFuncAttributeMaxDynamicSharedMemorySize, SMEM_TOTAL);

    prepack_w_kernel<<<4096, 256>>>(W);
    meta_main_kernel<<<128, 288, SMEM_TOTAL>>>(x1, x2, bv, out);
}